// round 15
// baseline (speedup 1.0000x reference)
#include <cuda_runtime.h>
#include <cuda_fp16.h>
#include <cstdint>

#define NN 100000
#define NE 1600000
#define FH 128
#define NG 256
#define NA 32

#define SCAN_BS 512
#define SCAN_NB ((NN + SCAN_BS - 1) / SCAN_BS)   // 196
#define DEGB 148                                  // deg blocks fused with GEMM1
#define NH4 (NN * FH / 8)                         // 1.6M uint4 in g_hh

// ---------------- scratch (device globals; no runtime allocation) ----------
// g_deg/g_stat/g_pool/g_cnt are zero on first call (static init) and re-zeroed
// at the tail of each call (k_mlp), keeping every graph replay identical.
__device__ __half    g_hh[(size_t)NN * FH];   // layer GEMM out (fp16)
__device__ __half    g_th[(size_t)NN * FH];   // layer-1 activation t (fp16)
__device__ int       g_deg[NN];
__device__ float     g_dinv[NN];
__device__ int       g_off[NN + 1];
__device__ int       g_cur[NN];
__device__ int       g_esrc[NE];
__device__ int       g_stat[SCAN_NB];         // decoupled-lookback status|value
__device__ float     g_pool[NG * FH];
__device__ int       g_cnt[NG];

// ---------------- helpers ---------------------------------------------------
__device__ __forceinline__ uint32_t smem_u32(const void* p) {
    uint32_t a;
    asm("{ .reg .u64 t; cvta.to.shared.u64 t, %1; cvt.u32.u64 %0, t; }"
        : "=r"(a) : "l"(p));
    return a;
}
__device__ __forceinline__ uint32_t h2u(float a, float b) {
    __half2 h = __floats2half2_rn(a, b);
    return *(uint32_t*)&h;
}
__device__ __forceinline__ void mma16816(float* c, const uint32_t* a,
                                         uint32_t b0, uint32_t b1) {
    asm volatile(
        "mma.sync.aligned.m16n8k16.row.col.f32.f16.f16.f32 "
        "{%0,%1,%2,%3}, {%4,%5,%6,%7}, {%8,%9}, {%0,%1,%2,%3};"
        : "+f"(c[0]), "+f"(c[1]), "+f"(c[2]), "+f"(c[3])
        : "r"(a[0]), "r"(a[1]), "r"(a[2]), "r"(a[3]), "r"(b0), "r"(b1));
}

// ---------------- single-kernel scan: decoupled lookback ---------------------
__global__ void k_scan() {
    __shared__ int s[SCAN_BS];
    __shared__ int sbase;
    int tid = threadIdx.x;
    int idx = blockIdx.x * SCAN_BS + tid;
    int v = (idx < NN) ? g_deg[idx] : 0;
    if (idx < NN) g_dinv[idx] = rsqrtf((float)v + 1.0f);
    s[tid] = v;
    __syncthreads();
    for (int d = 1; d < SCAN_BS; d <<= 1) {
        int t = (tid >= d) ? s[tid - d] : 0;
        __syncthreads();
        s[tid] += t;
        __syncthreads();
    }
    if (tid == 0) {
        int total = s[SCAN_BS - 1];
        int b = blockIdx.x;
        if (b == 0) {
            atomicExch(&g_stat[0], (2 << 30) | total);
            sbase = 0;
        } else {
            atomicExch(&g_stat[b], (1 << 30) | total);
            int run = 0;
            int j = b - 1;
            while (j >= 0) {
                int w = atomicAdd(&g_stat[j], 0);
                int st = ((unsigned)w) >> 30;
                if (st == 2) { run += w & 0x3FFFFFFF; break; }
                if (st == 1) { run += w & 0x3FFFFFFF; j--; }
            }
            atomicExch(&g_stat[b], (2 << 30) | (run + total));
            sbase = run;
        }
    }
    __syncthreads();
    int base = sbase;
    if (idx < NN) {
        int val = base + s[tid];
        g_off[idx + 1] = val;
        if (idx + 1 < NN) g_cur[idx + 1] = val;
    }
    if (idx == 0) { g_off[0] = 0; g_cur[0] = 0; }
}

// ---------------- CSR fill + g_hh dinv-prescale (uses fill's idle slots) ----
// Thread t: fill edge t (atomic cursor scatter, latency-bound) AND prescale
// uint4 #t of g_hh by dinv[row] (streaming, fills idle issue slots).
// NE == NN*FH/8, so the two index spaces coincide exactly.
__global__ void k_fill(const int* __restrict__ ei) {
    int t = blockIdx.x * blockDim.x + threadIdx.x;
    if (t >= NE) return;
    int src = __ldg(&ei[t]);
    int dst = __ldg(&ei[NE + t]);
    int p = atomicAdd(&g_cur[dst], 1);
    {   // prescale one uint4 (8 halves) of g_hh while the atomic is in flight
        uint4* H4 = (uint4*)g_hh;
        int row = t >> 4;
        __half2 d2 = __float2half2_rn(g_dinv[row]);
        uint4 v = H4[t];
        __half2* h = (__half2*)&v;
        h[0] = __hmul2(h[0], d2);
        h[1] = __hmul2(h[1], d2);
        h[2] = __hmul2(h[2], d2);
        h[3] = __hmul2(h[3], d2);
        H4[t] = v;
    }
    g_esrc[p] = src;
}

// ---------------- mma.sync GEMM (hi-only fp16 W) -----------------------------
// Blocks [0, auxb): int4 grid-stride degree histogram (RED/LTS pipe).
// Blocks [auxb, ...): 256 rows x 128 cols per CTA (2 sub-tiles, one W pack).
// W packed in-kernel from fp32 (L2-resident after first CTA).
// Y = scale .* (X @ W), fp16. scale = dinvp ? dinvp[row] : 1.
#define GEMM_SMEM (32768 + 32768)
__global__ void __launch_bounds__(256, 2)
k_gemm(const float* __restrict__ Xf, const __half* __restrict__ Xh,
       const float* __restrict__ W, __half* __restrict__ Y,
       const float* __restrict__ dinvp, const int* __restrict__ ei, int auxb) {
    int tid = threadIdx.x;
    if ((int)blockIdx.x < auxb) {
        int stride = auxb * 256;
        const int4* d4 = (const int4*)(ei + NE);
        for (int e4 = blockIdx.x * 256 + tid; e4 < NE / 4; e4 += stride) {
            int4 d = __ldg(&d4[e4]);
            atomicAdd(&g_deg[d.x], 1);
            atomicAdd(&g_deg[d.y], 1);
            atomicAdd(&g_deg[d.z], 1);
            atomicAdd(&g_deg[d.w], 1);
        }
        return;
    }
    extern __shared__ char sm[];
    char* Xs = sm;                            // [128 rows][16 chunks of 16B], swizzled
    uint2* Wsm = (uint2*)(sm + 32768);        // 4096 uint2 (32KB)
    int wid = tid >> 5, lane = tid & 31;
    int tile0 = (blockIdx.x - auxb) * 256;

    // in-kernel W pack: fp32 -> per-lane mma B fragments (hi)
#pragma unroll
    for (int i = 0; i < 16; i++) {
        int idx = tid + 256 * i;
        int ks = idx >> 9, nt = (idx >> 5) & 15, ln = idx & 31;
        int n = nt * 8 + (ln >> 2);
        uint32_t hh[2];
#pragma unroll
        for (int reg = 0; reg < 2; reg++) {
            int k = ks * 16 + (ln & 3) * 2 + reg * 8;
            __half2 hp = __halves2half2(__float2half_rn(__ldg(&W[k * FH + n])),
                                        __float2half_rn(__ldg(&W[(k + 1) * FH + n])));
            hh[reg] = *(uint32_t*)&hp;
        }
        Wsm[idx] = make_uint2(hh[0], hh[1]);
    }

    int wr = wid & 3;
    int wc = wid >> 2;
    uint32_t smx = smem_u32(Xs);

#pragma unroll
    for (int sub = 0; sub < 2; sub++) {
        int row0 = tile0 + sub * 128;
        if (row0 >= NN) break;                // uniform across CTA
        if (sub) __syncthreads();             // protect Xs reuse
        if (Xf) {
            const float4* X4 = (const float4*)Xf;
#pragma unroll
            for (int it = 0; it < 8; it++) {
                int g = tid + 256 * it;
                int r = g >> 4, c = g & 15;
                uint4 o = make_uint4(0, 0, 0, 0);
                if (row0 + r < NN) {
                    float4 a = X4[(size_t)(row0 + r) * 32 + c * 2];
                    float4 b = X4[(size_t)(row0 + r) * 32 + c * 2 + 1];
                    o.x = h2u(a.x, a.y); o.y = h2u(a.z, a.w);
                    o.z = h2u(b.x, b.y); o.w = h2u(b.z, b.w);
                }
                *(uint4*)(Xs + r * 256 + ((c ^ (r & 7)) * 16)) = o;
            }
        } else {
            const uint4* X4 = (const uint4*)Xh;
#pragma unroll
            for (int it = 0; it < 8; it++) {
                int g = tid + 256 * it;
                int r = g >> 4, c = g & 15;
                uint4 o = make_uint4(0, 0, 0, 0);
                if (row0 + r < NN) o = X4[(size_t)(row0 + r) * 16 + c];
                *(uint4*)(Xs + r * 256 + ((c ^ (r & 7)) * 16)) = o;
            }
        }
        __syncthreads();

        float acc[2][8][4];
#pragma unroll
        for (int mt = 0; mt < 2; mt++)
#pragma unroll
            for (int nt = 0; nt < 8; nt++)
#pragma unroll
                for (int q = 0; q < 4; q++) acc[mt][nt][q] = 0.f;

#pragma unroll
        for (int ks = 0; ks < 8; ks++) {
            uint32_t a[2][4];
#pragma unroll
            for (int mt = 0; mt < 2; mt++) {
                int sb2 = lane >> 3;
                int r = 32 * wr + 16 * mt + (lane & 7) + (sb2 & 1) * 8;
                int c = ks * 2 + (sb2 >> 1);
                uint32_t addr = smx + r * 256 + ((c ^ (r & 7)) * 16);
                asm volatile(
                    "ldmatrix.sync.aligned.m8n8.x4.shared.b16 {%0,%1,%2,%3}, [%4];"
                    : "=r"(a[mt][0]), "=r"(a[mt][1]), "=r"(a[mt][2]), "=r"(a[mt][3])
                    : "r"(addr));
            }
#pragma unroll
            for (int nt = 0; nt < 8; nt++) {
                int ntg = 8 * wc + nt;
                uint2 b = Wsm[(ks * 16 + ntg) * 32 + lane];
                mma16816(acc[0][nt], a[0], b.x, b.y);
                mma16816(acc[1][nt], a[1], b.x, b.y);
            }
        }

#pragma unroll
        for (int mt = 0; mt < 2; mt++) {
            int r0 = row0 + 32 * wr + 16 * mt + (lane >> 2);
            int r1 = r0 + 8;
            float s0 = 1.f, s1 = 1.f;
            if (dinvp) {
                s0 = (r0 < NN) ? dinvp[r0] : 0.f;
                s1 = (r1 < NN) ? dinvp[r1] : 0.f;
            }
#pragma unroll
            for (int nt = 0; nt < 8; nt++) {
                int col = 64 * wc + 8 * nt + (lane & 3) * 2;
                if (r0 < NN)
                    *(uint32_t*)&Y[(size_t)r0 * FH + col] =
                        h2u(acc[mt][nt][0] * s0, acc[mt][nt][1] * s0);
                if (r1 < NN)
                    *(uint32_t*)&Y[(size_t)r1 * FH + col] =
                        h2u(acc[mt][nt][2] * s1, acc[mt][nt][3] * s1);
            }
        }
    }
}

// ---------------- unified aggregation: prescaled H, HADD2 groups ------------
// out = relu(di*(sum_src H[src] + H[node]) + b);  H rows already dinv*h.
// POOL=0: write fp16 OutH.  POOL=1: smem-reduce into g_pool/g_cnt.
template <int POOL>
__global__ void __launch_bounds__(256)
k_agg(const __half* __restrict__ H, const float* __restrict__ bias,
      const int* __restrict__ batch, __half* __restrict__ OutH) {
    __shared__ float sp[8][128];
    __shared__ int sb[8];
    int warp = threadIdx.x >> 5;
    int lane = threadIdx.x & 31;
    int node = blockIdx.x * 8 + warp;
    int half = lane >> 4;
    int q    = lane & 15;
    int s = g_off[node];
    int e = g_off[node + 1];
    const uint4* H4 = (const uint4*)H;
    float a0 = 0.f, a1 = 0.f, a2 = 0.f, a3 = 0.f,
          a4 = 0.f, a5 = 0.f, a6 = 0.f, a7 = 0.f;
    int j = s + half;
    const __half2 hz = __float2half2_rn(0.f);
    while (j + 14 < e) {
        __half2 c0 = hz, c1 = hz, c2 = hz, c3 = hz;
#pragma unroll 2
        for (int u = 0; u < 8; u++) {
            int src = __ldg(&g_esrc[j + 2 * u]);
            uint4 v = __ldg(&H4[(size_t)src * 16 + q]);
            c0 = __hadd2(c0, *(__half2*)&v.x);
            c1 = __hadd2(c1, *(__half2*)&v.y);
            c2 = __hadd2(c2, *(__half2*)&v.z);
            c3 = __hadd2(c3, *(__half2*)&v.w);
        }
        float2 f;
        f = __half22float2(c0); a0 += f.x; a1 += f.y;
        f = __half22float2(c1); a2 += f.x; a3 += f.y;
        f = __half22float2(c2); a4 += f.x; a5 += f.y;
        f = __half22float2(c3); a6 += f.x; a7 += f.y;
        j += 16;
    }
    for (; j < e; j += 2) {   // remainder, exact fp32 path
        int src = __ldg(&g_esrc[j]);
        uint4 v = __ldg(&H4[(size_t)src * 16 + q]);
        float2 p;
        p = __half22float2(*(__half2*)&v.x); a0 += p.x; a1 += p.y;
        p = __half22float2(*(__half2*)&v.y); a2 += p.x; a3 += p.y;
        p = __half22float2(*(__half2*)&v.z); a4 += p.x; a5 += p.y;
        p = __half22float2(*(__half2*)&v.w); a6 += p.x; a7 += p.y;
    }
    a0 += __shfl_xor_sync(0xffffffffu, a0, 16);
    a1 += __shfl_xor_sync(0xffffffffu, a1, 16);
    a2 += __shfl_xor_sync(0xffffffffu, a2, 16);
    a3 += __shfl_xor_sync(0xffffffffu, a3, 16);
    a4 += __shfl_xor_sync(0xffffffffu, a4, 16);
    a5 += __shfl_xor_sync(0xffffffffu, a5, 16);
    a6 += __shfl_xor_sync(0xffffffffu, a6, 16);
    a7 += __shfl_xor_sync(0xffffffffu, a7, 16);
    if (half == 0) {
        {   // self term (row already dinv*h)
            uint4 v = __ldg(&H4[(size_t)node * 16 + q]);
            float2 p;
            p = __half22float2(*(__half2*)&v.x); a0 += p.x; a1 += p.y;
            p = __half22float2(*(__half2*)&v.y); a2 += p.x; a3 += p.y;
            p = __half22float2(*(__half2*)&v.z); a4 += p.x; a5 += p.y;
            p = __half22float2(*(__half2*)&v.w); a6 += p.x; a7 += p.y;
        }
        float di = g_dinv[node];
        const float4* B4 = (const float4*)bias;
        float4 bv0 = __ldg(&B4[2 * q]);
        float4 bv1 = __ldg(&B4[2 * q + 1]);
        float r0 = fmaxf(di * a0 + bv0.x, 0.f);
        float r1 = fmaxf(di * a1 + bv0.y, 0.f);
        float r2 = fmaxf(di * a2 + bv0.z, 0.f);
        float r3 = fmaxf(di * a3 + bv0.w, 0.f);
        float r4 = fmaxf(di * a4 + bv1.x, 0.f);
        float r5 = fmaxf(di * a5 + bv1.y, 0.f);
        float r6 = fmaxf(di * a6 + bv1.z, 0.f);
        float r7 = fmaxf(di * a7 + bv1.w, 0.f);
        if (POOL == 0) {
            uint4 o;
            o.x = h2u(r0, r1); o.y = h2u(r2, r3);
            o.z = h2u(r4, r5); o.w = h2u(r6, r7);
            ((uint4*)OutH)[(size_t)node * 16 + q] = o;
        } else {
            *(float4*)&sp[warp][8 * q]     = make_float4(r0, r1, r2, r3);
            *(float4*)&sp[warp][8 * q + 4] = make_float4(r4, r5, r6, r7);
        }
    }
    if (POOL == 1) {
        if (lane == 0) sb[warp] = __ldg(&batch[node]);
        __syncthreads();
        int t = threadIdx.x;
        int bg = sb[0];
        bool uni = true;
#pragma unroll
        for (int w = 1; w < 8; w++) uni &= (sb[w] == bg);
        if (t < 128) {
            if (uni) {
                float sum = 0.f;
#pragma unroll
                for (int w = 0; w < 8; w++) sum += sp[w][t];
                atomicAdd(&g_pool[bg * FH + t], sum);
            } else {
#pragma unroll
                for (int w = 0; w < 8; w++)
                    atomicAdd(&g_pool[sb[w] * FH + t], sp[w][t]);
            }
        } else if (uni) {
            if (t == 128) atomicAdd(&g_cnt[bg], 8);
        } else {
            if (t >= 128 && t < 136) atomicAdd(&g_cnt[sb[t - 128]], 1);
        }
    }
}

// ---------------- MLP head + tail re-zeroing for the next replay -------------
__global__ void k_mlp(const float* __restrict__ Wl1, const float* __restrict__ bl1,
                      const float* __restrict__ Wl2, const float* __restrict__ bl2,
                      float* __restrict__ out) {
    int tid = threadIdx.x;
    if (blockIdx.x >= NG) {
        int i = (blockIdx.x - NG) * FH + tid;
        if (i < NN) g_deg[i] = 0;
        if (i < SCAN_NB) g_stat[i] = 0;
        return;
    }
    __shared__ float gv[FH];
    __shared__ float tv[FH];
    int b = blockIdx.x;
    float c = fmaxf((float)g_cnt[b], 1.0f);
    gv[tid] = g_pool[b * FH + tid] / c;
    __syncthreads();
    g_pool[b * FH + tid] = 0.f;
    if (tid == 0) g_cnt[b] = 0;
    float s = bl1[tid];
#pragma unroll 8
    for (int k = 0; k < FH; k++) s += gv[k] * Wl1[k * FH + tid];
    tv[tid] = fmaxf(s, 0.f);
    __syncthreads();
    if (tid < NA) {
        float o = bl2[tid];
#pragma unroll 8
        for (int k = 0; k < FH; k++) o += tv[k] * Wl2[k * NA + tid];
        out[b * NA + tid] = o;
    }
}

// ---------------- launch ----------------------------------------------------
extern "C" void kernel_launch(void* const* d_in, const int* in_sizes, int n_in,
                              void* d_out, int out_size) {
    const float* x   = (const float*)d_in[0];
    const int*   ei  = (const int*)d_in[1];
    const int*   bat = (const int*)d_in[2];
    const float* W1  = (const float*)d_in[3];
    const float* b1  = (const float*)d_in[4];
    const float* W2  = (const float*)d_in[5];
    const float* b2  = (const float*)d_in[6];
    const float* Wl1 = (const float*)d_in[7];
    const float* bl1 = (const float*)d_in[8];
    const float* Wl2 = (const float*)d_in[9];
    const float* bl2 = (const float*)d_in[10];
    float* out = (float*)d_out;

    __half *phh = nullptr, *pth = nullptr;
    float* pdinv = nullptr;
    cudaGetSymbolAddress((void**)&phh, g_hh);
    cudaGetSymbolAddress((void**)&pth, g_th);
    cudaGetSymbolAddress((void**)&pdinv, g_dinv);

    cudaFuncSetAttribute(k_gemm, cudaFuncAttributeMaxDynamicSharedMemorySize,
                         GEMM_SMEM);

    const int GB = (NN + 255) / 256;     // 391
    const int AB = NN / 8;               // 12500
    const int ZB = (NN + FH - 1) / FH;   // 782 tail zero blocks

    // 1: fused degree histogram (148 blocks) + layer-1 GEMM (hi-only, unscaled)
    k_gemm<<<DEGB + GB, 256, GEMM_SMEM>>>(x, nullptr, W1, phh,
                                          nullptr, ei, DEGB);
    // 2: single-pass scan (dinv + off + cur)
    k_scan<<<SCAN_NB, SCAN_BS>>>();
    // 3: CSR fill + in-place dinv-prescale of g_hh (idle-slot overlap)
    k_fill<<<(NE + 255) / 256, 256>>>(ei);
    // 4: agg layer 1 (prescaled, HADD2 groups)  [profiled slot]
    k_agg<0><<<AB, 256>>>(phh, b1, bat, pth);
    // 5: layer-2 GEMM, hi-only fp16, dinv-prescaled out
    k_gemm<<<GB, 256, GEMM_SMEM>>>(nullptr, pth, W2, phh,
                                   pdinv, ei, 0);
    // 6: agg layer 2 (prescaled, HADD2 groups) + pooling
    k_agg<1><<<AB, 256>>>(phh, b2, bat, nullptr);
    // 7: MLP head + tail zeroing (deg/stat/pool/cnt) for next replay
    k_mlp<<<NG + ZB, FH>>>(Wl1, bl1, Wl2, bl2, out);
}

// round 16
// speedup vs baseline: 1.0898x; 1.0898x over previous
#include <cuda_runtime.h>
#include <cuda_fp16.h>
#include <cstdint>

#define NN 100000
#define NE 1600000
#define FH 128
#define NG 256
#define NA 32

#define SCAN_BS 512
#define SCAN_NB ((NN + SCAN_BS - 1) / SCAN_BS)   // 196
#define DEGB 148                                  // deg blocks fused with GEMM1

// ---------------- scratch (device globals; no runtime allocation) ----------
// g_deg/g_stat/g_pool/g_cnt are zero on first call (static init) and re-zeroed
// at the tail of each call (k_mlp), keeping every graph replay identical.
__device__ __half    g_hh[(size_t)NN * FH];   // layer GEMM out (fp16, unscaled)
__device__ __half    g_th[(size_t)NN * FH];   // layer-1 activation t (fp16)
__device__ int       g_deg[NN];
__device__ float     g_dinv[NN];
__device__ uint32_t  g_dh2[NN];               // dinv as duplicated half2
__device__ int       g_off[NN + 1];
__device__ int       g_cur[NN];
__device__ int       g_esrc[NE];
__device__ int       g_stat[SCAN_NB];         // decoupled-lookback status|value
__device__ float     g_pool[NG * FH];
__device__ int       g_cnt[NG];

// ---------------- helpers ---------------------------------------------------
__device__ __forceinline__ uint32_t smem_u32(const void* p) {
    uint32_t a;
    asm("{ .reg .u64 t; cvta.to.shared.u64 t, %1; cvt.u32.u64 %0, t; }"
        : "=r"(a) : "l"(p));
    return a;
}
__device__ __forceinline__ uint32_t h2u(float a, float b) {
    __half2 h = __floats2half2_rn(a, b);
    return *(uint32_t*)&h;
}
__device__ __forceinline__ void mma16816(float* c, const uint32_t* a,
                                         uint32_t b0, uint32_t b1) {
    asm volatile(
        "mma.sync.aligned.m16n8k16.row.col.f32.f16.f16.f32 "
        "{%0,%1,%2,%3}, {%4,%5,%6,%7}, {%8,%9}, {%0,%1,%2,%3};"
        : "+f"(c[0]), "+f"(c[1]), "+f"(c[2]), "+f"(c[3])
        : "r"(a[0]), "r"(a[1]), "r"(a[2]), "r"(a[3]), "r"(b0), "r"(b1));
}

// ---------------- single-kernel scan: decoupled lookback ---------------------
__global__ void k_scan() {
    __shared__ int s[SCAN_BS];
    __shared__ int sbase;
    int tid = threadIdx.x;
    int idx = blockIdx.x * SCAN_BS + tid;
    int v = (idx < NN) ? g_deg[idx] : 0;
    if (idx < NN) {
        float di = rsqrtf((float)v + 1.0f);
        g_dinv[idx] = di;
        __half2 d2 = __float2half2_rn(di);
        g_dh2[idx] = *(uint32_t*)&d2;
    }
    s[tid] = v;
    __syncthreads();
    for (int d = 1; d < SCAN_BS; d <<= 1) {
        int t = (tid >= d) ? s[tid - d] : 0;
        __syncthreads();
        s[tid] += t;
        __syncthreads();
    }
    if (tid == 0) {
        int total = s[SCAN_BS - 1];
        int b = blockIdx.x;
        if (b == 0) {
            atomicExch(&g_stat[0], (2 << 30) | total);
            sbase = 0;
        } else {
            atomicExch(&g_stat[b], (1 << 30) | total);
            int run = 0;
            int j = b - 1;
            while (j >= 0) {
                int w = atomicAdd(&g_stat[j], 0);
                int st = ((unsigned)w) >> 30;
                if (st == 2) { run += w & 0x3FFFFFFF; break; }
                if (st == 1) { run += w & 0x3FFFFFFF; j--; }
            }
            atomicExch(&g_stat[b], (2 << 30) | (run + total));
            sbase = run;
        }
    }
    __syncthreads();
    int base = sbase;
    if (idx < NN) {
        int val = base + s[tid];
        g_off[idx + 1] = val;
        if (idx + 1 < NN) g_cur[idx + 1] = val;
    }
    if (idx == 0) { g_off[0] = 0; g_cur[0] = 0; }
}

// ---------------- CSR fill: 1 edge/thread (validated fastest form) ----------
__global__ void k_fill(const int* __restrict__ ei) {
    int e = blockIdx.x * blockDim.x + threadIdx.x;
    if (e < NE) {
        int src = __ldg(&ei[e]);
        int dst = __ldg(&ei[NE + e]);
        g_esrc[atomicAdd(&g_cur[dst], 1)] = src;
    }
}

// ---------------- mma.sync GEMM (hi-only fp16 W) -----------------------------
// Blocks [0, auxb): int4 grid-stride degree histogram (RED/LTS pipe).
// Blocks [auxb, ...): 256 rows x 128 cols per CTA (2 sub-tiles, one W pack).
// W packed in-kernel from fp32 (L2-resident after first CTA).
// Y = scale .* (X @ W), fp16. scale = dinvp ? dinvp[row] : 1.
#define GEMM_SMEM (32768 + 32768)
__global__ void __launch_bounds__(256, 2)
k_gemm(const float* __restrict__ Xf, const __half* __restrict__ Xh,
       const float* __restrict__ W, __half* __restrict__ Y,
       const float* __restrict__ dinvp, const int* __restrict__ ei, int auxb) {
    int tid = threadIdx.x;
    if ((int)blockIdx.x < auxb) {
        int stride = auxb * 256;
        const int4* d4 = (const int4*)(ei + NE);
        for (int e4 = blockIdx.x * 256 + tid; e4 < NE / 4; e4 += stride) {
            int4 d = __ldg(&d4[e4]);
            atomicAdd(&g_deg[d.x], 1);
            atomicAdd(&g_deg[d.y], 1);
            atomicAdd(&g_deg[d.z], 1);
            atomicAdd(&g_deg[d.w], 1);
        }
        return;
    }
    extern __shared__ char sm[];
    char* Xs = sm;                            // [128 rows][16 chunks of 16B], swizzled
    uint2* Wsm = (uint2*)(sm + 32768);        // 4096 uint2 (32KB)
    int wid = tid >> 5, lane = tid & 31;
    int tile0 = (blockIdx.x - auxb) * 256;

    // in-kernel W pack: fp32 -> per-lane mma B fragments (hi)
#pragma unroll
    for (int i = 0; i < 16; i++) {
        int idx = tid + 256 * i;
        int ks = idx >> 9, nt = (idx >> 5) & 15, ln = idx & 31;
        int n = nt * 8 + (ln >> 2);
        uint32_t hh[2];
#pragma unroll
        for (int reg = 0; reg < 2; reg++) {
            int k = ks * 16 + (ln & 3) * 2 + reg * 8;
            __half2 hp = __halves2half2(__float2half_rn(__ldg(&W[k * FH + n])),
                                        __float2half_rn(__ldg(&W[(k + 1) * FH + n])));
            hh[reg] = *(uint32_t*)&hp;
        }
        Wsm[idx] = make_uint2(hh[0], hh[1]);
    }

    int wr = wid & 3;
    int wc = wid >> 2;
    uint32_t smx = smem_u32(Xs);

#pragma unroll
    for (int sub = 0; sub < 2; sub++) {
        int row0 = tile0 + sub * 128;
        if (row0 >= NN) break;                // uniform across CTA
        if (sub) __syncthreads();             // protect Xs reuse
        if (Xf) {
            const float4* X4 = (const float4*)Xf;
#pragma unroll
            for (int it = 0; it < 8; it++) {
                int g = tid + 256 * it;
                int r = g >> 4, c = g & 15;
                uint4 o = make_uint4(0, 0, 0, 0);
                if (row0 + r < NN) {
                    float4 a = X4[(size_t)(row0 + r) * 32 + c * 2];
                    float4 b = X4[(size_t)(row0 + r) * 32 + c * 2 + 1];
                    o.x = h2u(a.x, a.y); o.y = h2u(a.z, a.w);
                    o.z = h2u(b.x, b.y); o.w = h2u(b.z, b.w);
                }
                *(uint4*)(Xs + r * 256 + ((c ^ (r & 7)) * 16)) = o;
            }
        } else {
            const uint4* X4 = (const uint4*)Xh;
#pragma unroll
            for (int it = 0; it < 8; it++) {
                int g = tid + 256 * it;
                int r = g >> 4, c = g & 15;
                uint4 o = make_uint4(0, 0, 0, 0);
                if (row0 + r < NN) o = X4[(size_t)(row0 + r) * 16 + c];
                *(uint4*)(Xs + r * 256 + ((c ^ (r & 7)) * 16)) = o;
            }
        }
        __syncthreads();

        float acc[2][8][4];
#pragma unroll
        for (int mt = 0; mt < 2; mt++)
#pragma unroll
            for (int nt = 0; nt < 8; nt++)
#pragma unroll
                for (int q = 0; q < 4; q++) acc[mt][nt][q] = 0.f;

#pragma unroll
        for (int ks = 0; ks < 8; ks++) {
            uint32_t a[2][4];
#pragma unroll
            for (int mt = 0; mt < 2; mt++) {
                int sb2 = lane >> 3;
                int r = 32 * wr + 16 * mt + (lane & 7) + (sb2 & 1) * 8;
                int c = ks * 2 + (sb2 >> 1);
                uint32_t addr = smx + r * 256 + ((c ^ (r & 7)) * 16);
                asm volatile(
                    "ldmatrix.sync.aligned.m8n8.x4.shared.b16 {%0,%1,%2,%3}, [%4];"
                    : "=r"(a[mt][0]), "=r"(a[mt][1]), "=r"(a[mt][2]), "=r"(a[mt][3])
                    : "r"(addr));
            }
#pragma unroll
            for (int nt = 0; nt < 8; nt++) {
                int ntg = 8 * wc + nt;
                uint2 b = Wsm[(ks * 16 + ntg) * 32 + lane];
                mma16816(acc[0][nt], a[0], b.x, b.y);
                mma16816(acc[1][nt], a[1], b.x, b.y);
            }
        }

#pragma unroll
        for (int mt = 0; mt < 2; mt++) {
            int r0 = row0 + 32 * wr + 16 * mt + (lane >> 2);
            int r1 = r0 + 8;
            float s0 = 1.f, s1 = 1.f;
            if (dinvp) {
                s0 = (r0 < NN) ? dinvp[r0] : 0.f;
                s1 = (r1 < NN) ? dinvp[r1] : 0.f;
            }
#pragma unroll
            for (int nt = 0; nt < 8; nt++) {
                int col = 64 * wc + 8 * nt + (lane & 3) * 2;
                if (r0 < NN)
                    *(uint32_t*)&Y[(size_t)r0 * FH + col] =
                        h2u(acc[mt][nt][0] * s0, acc[mt][nt][1] * s0);
                if (r1 < NN)
                    *(uint32_t*)&Y[(size_t)r1 * FH + col] =
                        h2u(acc[mt][nt][2] * s1, acc[mt][nt][3] * s1);
            }
        }
    }
}

// ---------------- unified aggregation: single fp16 path, no groups ----------
// SCALE=1: H unscaled, per-edge *dinv[src] via g_dh2 (HFMA2); self = di*H[d].
// SCALE=0: H prescaled (HADD2); self = H[d].
// POOL=0: write fp16 OutH.  POOL=1: smem-reduce into g_pool/g_cnt.
template <int SCALE, int POOL>
__global__ void __launch_bounds__(256)
k_agg(const __half* __restrict__ H, const float* __restrict__ bias,
      const int* __restrict__ batch, __half* __restrict__ OutH) {
    __shared__ float sp[8][128];
    __shared__ int sb[8];
    int warp = threadIdx.x >> 5;
    int lane = threadIdx.x & 31;
    int node = blockIdx.x * 8 + warp;
    int half = lane >> 4;
    int q    = lane & 15;
    int s = g_off[node];
    int e = g_off[node + 1];
    const uint4* H4 = (const uint4*)H;
    const __half2 hzz = __float2half2_rn(0.f);
    __half2 c0 = hzz, c1 = hzz, c2 = hzz, c3 = hzz;
#pragma unroll 4
    for (int j = s + half; j < e; j += 2) {
        int src = __ldg(&g_esrc[j]);
        uint4 v = __ldg(&H4[(size_t)src * 16 + q]);
        if (SCALE) {
            uint32_t du = __ldg(&g_dh2[src]);
            __half2 cd = *(__half2*)&du;
            c0 = __hfma2(*(__half2*)&v.x, cd, c0);
            c1 = __hfma2(*(__half2*)&v.y, cd, c1);
            c2 = __hfma2(*(__half2*)&v.z, cd, c2);
            c3 = __hfma2(*(__half2*)&v.w, cd, c3);
        } else {
            c0 = __hadd2(c0, *(__half2*)&v.x);
            c1 = __hadd2(c1, *(__half2*)&v.y);
            c2 = __hadd2(c2, *(__half2*)&v.z);
            c3 = __hadd2(c3, *(__half2*)&v.w);
        }
    }
    float a0, a1, a2, a3, a4, a5, a6, a7;
    {
        float2 f;
        f = __half22float2(c0); a0 = f.x; a1 = f.y;
        f = __half22float2(c1); a2 = f.x; a3 = f.y;
        f = __half22float2(c2); a4 = f.x; a5 = f.y;
        f = __half22float2(c3); a6 = f.x; a7 = f.y;
    }
    a0 += __shfl_xor_sync(0xffffffffu, a0, 16);
    a1 += __shfl_xor_sync(0xffffffffu, a1, 16);
    a2 += __shfl_xor_sync(0xffffffffu, a2, 16);
    a3 += __shfl_xor_sync(0xffffffffu, a3, 16);
    a4 += __shfl_xor_sync(0xffffffffu, a4, 16);
    a5 += __shfl_xor_sync(0xffffffffu, a5, 16);
    a6 += __shfl_xor_sync(0xffffffffu, a6, 16);
    a7 += __shfl_xor_sync(0xffffffffu, a7, 16);
    if (half == 0) {
        float di = g_dinv[node];
        {   // self term, exact fp32: SCALE ? di*H[d] : H[d] (already dinv*h)
            float c = SCALE ? di : 1.f;
            uint4 v = __ldg(&H4[(size_t)node * 16 + q]);
            float2 p;
            p = __half22float2(*(__half2*)&v.x); a0 += c * p.x; a1 += c * p.y;
            p = __half22float2(*(__half2*)&v.y); a2 += c * p.x; a3 += c * p.y;
            p = __half22float2(*(__half2*)&v.z); a4 += c * p.x; a5 += c * p.y;
            p = __half22float2(*(__half2*)&v.w); a6 += c * p.x; a7 += c * p.y;
        }
        const float4* B4 = (const float4*)bias;
        float4 bv0 = __ldg(&B4[2 * q]);
        float4 bv1 = __ldg(&B4[2 * q + 1]);
        float r0 = fmaxf(di * a0 + bv0.x, 0.f);
        float r1 = fmaxf(di * a1 + bv0.y, 0.f);
        float r2 = fmaxf(di * a2 + bv0.z, 0.f);
        float r3 = fmaxf(di * a3 + bv0.w, 0.f);
        float r4 = fmaxf(di * a4 + bv1.x, 0.f);
        float r5 = fmaxf(di * a5 + bv1.y, 0.f);
        float r6 = fmaxf(di * a6 + bv1.z, 0.f);
        float r7 = fmaxf(di * a7 + bv1.w, 0.f);
        if (POOL == 0) {
            uint4 o;
            o.x = h2u(r0, r1); o.y = h2u(r2, r3);
            o.z = h2u(r4, r5); o.w = h2u(r6, r7);
            ((uint4*)OutH)[(size_t)node * 16 + q] = o;
        } else {
            *(float4*)&sp[warp][8 * q]     = make_float4(r0, r1, r2, r3);
            *(float4*)&sp[warp][8 * q + 4] = make_float4(r4, r5, r6, r7);
        }
    }
    if (POOL == 1) {
        if (lane == 0) sb[warp] = __ldg(&batch[node]);
        __syncthreads();
        int t = threadIdx.x;
        int bg = sb[0];
        bool uni = true;
#pragma unroll
        for (int w = 1; w < 8; w++) uni &= (sb[w] == bg);
        if (t < 128) {
            if (uni) {
                float sum = 0.f;
#pragma unroll
                for (int w = 0; w < 8; w++) sum += sp[w][t];
                atomicAdd(&g_pool[bg * FH + t], sum);
            } else {
#pragma unroll
                for (int w = 0; w < 8; w++)
                    atomicAdd(&g_pool[sb[w] * FH + t], sp[w][t]);
            }
        } else if (uni) {
            if (t == 128) atomicAdd(&g_cnt[bg], 8);
        } else {
            if (t >= 128 && t < 136) atomicAdd(&g_cnt[sb[t - 128]], 1);
        }
    }
}

// ---------------- MLP head + tail re-zeroing for the next replay -------------
__global__ void k_mlp(const float* __restrict__ Wl1, const float* __restrict__ bl1,
                      const float* __restrict__ Wl2, const float* __restrict__ bl2,
                      float* __restrict__ out) {
    int tid = threadIdx.x;
    if (blockIdx.x >= NG) {
        int i = (blockIdx.x - NG) * FH + tid;
        if (i < NN) g_deg[i] = 0;
        if (i < SCAN_NB) g_stat[i] = 0;
        return;
    }
    __shared__ float gv[FH];
    __shared__ float tv[FH];
    int b = blockIdx.x;
    float c = fmaxf((float)g_cnt[b], 1.0f);
    gv[tid] = g_pool[b * FH + tid] / c;
    __syncthreads();
    g_pool[b * FH + tid] = 0.f;
    if (tid == 0) g_cnt[b] = 0;
    float s = bl1[tid];
#pragma unroll 8
    for (int k = 0; k < FH; k++) s += gv[k] * Wl1[k * FH + tid];
    tv[tid] = fmaxf(s, 0.f);
    __syncthreads();
    if (tid < NA) {
        float o = bl2[tid];
#pragma unroll 8
        for (int k = 0; k < FH; k++) o += tv[k] * Wl2[k * NA + tid];
        out[b * NA + tid] = o;
    }
}

// ---------------- launch ----------------------------------------------------
extern "C" void kernel_launch(void* const* d_in, const int* in_sizes, int n_in,
                              void* d_out, int out_size) {
    const float* x   = (const float*)d_in[0];
    const int*   ei  = (const int*)d_in[1];
    const int*   bat = (const int*)d_in[2];
    const float* W1  = (const float*)d_in[3];
    const float* b1  = (const float*)d_in[4];
    const float* W2  = (const float*)d_in[5];
    const float* b2  = (const float*)d_in[6];
    const float* Wl1 = (const float*)d_in[7];
    const float* bl1 = (const float*)d_in[8];
    const float* Wl2 = (const float*)d_in[9];
    const float* bl2 = (const float*)d_in[10];
    float* out = (float*)d_out;

    __half *phh = nullptr, *pth = nullptr;
    float* pdinv = nullptr;
    cudaGetSymbolAddress((void**)&phh, g_hh);
    cudaGetSymbolAddress((void**)&pth, g_th);
    cudaGetSymbolAddress((void**)&pdinv, g_dinv);

    cudaFuncSetAttribute(k_gemm, cudaFuncAttributeMaxDynamicSharedMemorySize,
                         GEMM_SMEM);

    const int GB = (NN + 255) / 256;     // 391
    const int AB = NN / 8;               // 12500
    const int ZB = (NN + FH - 1) / FH;   // 782 tail zero blocks

    // 1: fused degree histogram (148 blocks) + layer-1 GEMM (hi-only, unscaled)
    k_gemm<<<DEGB + GB, 256, GEMM_SMEM>>>(x, nullptr, W1, phh,
                                          nullptr, ei, DEGB);
    // 2: single-pass scan (dinv + dh2 + off + cur)
    k_scan<<<SCAN_NB, SCAN_BS>>>();
    // 3: CSR fill, 1 edge/thread
    k_fill<<<(NE + 255) / 256, 256>>>(ei);
    // 4: agg layer 1 (single fp16 path, per-edge dinv)  [profiled slot]
    k_agg<1, 0><<<AB, 256>>>(phh, b1, bat, pth);
    // 5: layer-2 GEMM, hi-only fp16, dinv-prescaled out
    k_gemm<<<GB, 256, GEMM_SMEM>>>(nullptr, pth, W2, phh,
                                   pdinv, ei, 0);
    // 6: agg layer 2 (single fp16 path, prescaled) + pooling
    k_agg<0, 1><<<AB, 256>>>(phh, b2, bat, nullptr);
    // 7: MLP head + tail zeroing (deg/stat/pool/cnt) for next replay
    k_mlp<<<NG + ZB, FH>>>(Wl1, bl1, Wl2, bl2, out);
}